// round 15
// baseline (speedup 1.0000x reference)
#include <cuda_runtime.h>
#include <cstdint>

#define AANCH 69354
#define APAD  69376
#define NCLS  80
#define TOPK  1000
#define KPAD  1024
#define CAND  2048
#define NSUB  8
#define SUBCAP 256
#define SCORE_TH 0.05f
#define IOU_TH   0.5f
#define T1GUESS  0.1955f

#define NELEM4     1387080         // AANCH*NCLS/4
#define DEC_BLOCKS 271             // ceil(AANCH/256)
#define EMIT_BLOCKS 5419           // ceil(NELEM4/256)

typedef unsigned int u32;
typedef unsigned long long u64;

// ---- device scratch (no allocations allowed) ----
__device__ float  g_boxes[AANCH * 4];
__device__ u64    g_cand[NCLS * NSUB * SUBCAP];   // 8 sub-buffers per class
__device__ int    g_ccnt[NCLS * NSUB];            // zero-init; reset by sortb
__device__ float4 g_cbox[NCLS * KPAD];
__device__ float  g_car[NCLS * KPAD];
__device__ float  g_csc[NCLS * KPAD];
__device__ u32    g_valid[NCLS * 32];
// mask transposed: [class][word 0..31][row 0..1023]
__device__ u32    g_mask[(size_t)NCLS * 32 * 1024];

// ============================================================
// Kernel 1: fused decode + candidate emission (8-way split counters)
// ============================================================
__global__ void __launch_bounds__(256)
prep_kernel(const float* __restrict__ anchors,
            const float* __restrict__ regr,
            const float* __restrict__ cls,
            const int* __restrict__ ph,
            const int* __restrict__ pw) {
    int b = blockIdx.x;
    if (b < DEC_BLOCKS) {
        int a = b * 256 + threadIdx.x;
        if (a >= AANCH) return;
        float W = pw ? (float)(*pw) : 608.0f;
        float H = ph ? (float)(*ph) : 608.0f;
        float4 an = ((const float4*)anchors)[a];
        float4 dl = ((const float4*)regr)[a];
        float w = an.z - an.x;
        float h = an.w - an.y;
        float cx = an.x + 0.5f * w;
        float cy = an.y + 0.5f * h;
        float dx = dl.x * 0.1f, dy = dl.y * 0.1f;
        float dw = dl.z * 0.2f, dh = dl.w * 0.2f;
        float pcx = cx + dx * w;
        float pcy = cy + dy * h;
        float pwid = expf(dw) * w;
        float phgt = expf(dh) * h;
        float x1 = fminf(fmaxf(pcx - 0.5f * pwid, 0.0f), W);
        float y1 = fminf(fmaxf(pcy - 0.5f * phgt, 0.0f), H);
        float x2 = fminf(fmaxf(pcx + 0.5f * pwid, 0.0f), W);
        float y2 = fminf(fmaxf(pcy + 0.5f * phgt, 0.0f), H);
        ((float4*)g_boxes)[a] = make_float4(x1, y1, x2, y2);
    } else {
        int i = (b - DEC_BLOCKS) * 256 + threadIdx.x;   // float4 index
        const int sub = b & 7;
        if (i < NELEM4) {
            float4 v = ((const float4*)cls)[i];
            int e = i * 4;
            int a = e / NCLS;
            int c = e % NCLS;          // NCLS%4==0 -> c in {0,4,...,76}
#pragma unroll
            for (int q = 0; q < 4; q++) {
                float s = (q == 0) ? v.x : (q == 1) ? v.y : (q == 2) ? v.z : v.w;
                if (s > T1GUESS) {
                    int slot = (c + q) * NSUB + sub;
                    int p = atomicAdd(&g_ccnt[slot], 1);
                    if (p < SUBCAP)
                        g_cand[slot * SUBCAP + p] =
                            ((u64)__float_as_uint(s) << 32) | (u32)(~(u32)a);
                }
            }
        }
    }
}

// ============================================================
// Kernel 2: per-class segment-load + sort + candidate tables.
// grid=80, block=512.
// ============================================================
__device__ __forceinline__ int bin_of(float s) {
    int b = (int)((s - SCORE_TH) * (32.0f / 0.15f));
    return min(max(b, 0), 31);
}

__global__ void __launch_bounds__(512)
sortb_kernel(const float* __restrict__ cls) {
    __shared__ u64 keys[CAND];
    __shared__ u32 bincnt[32];
    __shared__ u32 wbin[16][32];
    __shared__ int s_cnts[NSUB], s_off[NSUB], s_ok;
    __shared__ int s_cnt, s_b1, s_need, s_b2;

    const int c = blockIdx.x;
    const int tid = threadIdx.x, lane = tid & 31, warp = tid >> 5;

    if (tid < NSUB) s_cnts[tid] = g_ccnt[c * NSUB + tid];
    __syncthreads();
    if (tid == 0) {
        int tot = 0, ovf = 0;
        for (int s = 0; s < NSUB; s++) {
            s_off[s] = tot;
            if (s_cnts[s] > SUBCAP) ovf = 1;
            tot += min(s_cnts[s], SUBCAP);
        }
        s_cnt = tot;
        s_ok = (!ovf && tot >= TOPK && tot <= CAND) ? 1 : 0;
    }
    __syncthreads();
    const bool ok = (s_ok != 0);

    for (int i = tid; i < CAND; i += 512) keys[i] = 0ull;
    __syncthreads();

    if (ok) {
        // concatenate the 8 segments
#pragma unroll
        for (int s = 0; s < NSUB; s++) {
            int n = min(s_cnts[s], SUBCAP);
            int off = s_off[s];
            const u64* seg = g_cand + (c * NSUB + s) * SUBCAP;
            for (int i = tid; i < n; i += 512) keys[off + i] = seg[i];
        }
    } else {
        // ---- exact fallback: 2-level ballot histogram on strided cls ----
        if (tid == 0) s_cnt = 0;
        __syncthreads();
        const int NITER = (APAD + 511) / 512;
        {
            u32 bc = 0;
            for (int it = 0; it < NITER; it++) {
                int a = tid + it * 512;
                float s = (a < AANCH) ? cls[(size_t)a * NCLS + c] : -1.0f;
                bool ir = s > SCORE_TH;
                int bin = ir ? bin_of(s) : 0;
                u32 m = __ballot_sync(0xffffffffu, ir);
#pragma unroll
                for (int bb = 0; bb < 5; bb++) {
                    u32 vb = __ballot_sync(0xffffffffu, (bin >> bb) & 1);
                    m &= ((lane >> bb) & 1) ? vb : ~vb;
                }
                bc += __popc(m);
            }
            wbin[warp][lane] = bc;
        }
        __syncthreads();
        if (tid < 32) {
            u32 acc = 0;
#pragma unroll
            for (int w = 0; w < 16; w++) acc += wbin[w][tid];
            bincnt[tid] = acc;
        }
        __syncthreads();
        if (tid == 0) {
            int tot = 0, b1 = 0, found = 0;
            for (int b = 31; b >= 0; b--) {
                if (tot + (int)bincnt[b] >= TOPK) { b1 = b; found = 1; break; }
                tot += (int)bincnt[b];
            }
            s_b1 = found ? b1 : 0;
            s_need = TOPK - tot;
            s_b2 = 0;
        }
        __syncthreads();
        const int b1 = s_b1;
        const float w1 = 0.15f / 32.0f;
        const float lo1 = SCORE_TH + b1 * w1;
        {
            u32 bc = 0;
            for (int it = 0; it < NITER; it++) {
                int a = tid + it * 512;
                float s = (a < AANCH) ? cls[(size_t)a * NCLS + c] : -1.0f;
                bool ir = s > SCORE_TH;
                bool inb = ir && (bin_of(s) == b1);
                int sub = 0;
                if (inb) sub = min(max((int)((s - lo1) * (32.0f / w1)), 0), 31);
                u32 m = __ballot_sync(0xffffffffu, inb);
#pragma unroll
                for (int bb = 0; bb < 5; bb++) {
                    u32 vb = __ballot_sync(0xffffffffu, (sub >> bb) & 1);
                    m &= ((lane >> bb) & 1) ? vb : ~vb;
                }
                bc += __popc(m);
            }
            wbin[warp][lane] = bc;
        }
        __syncthreads();
        if (tid < 32) {
            u32 acc = 0;
#pragma unroll
            for (int w = 0; w < 16; w++) acc += wbin[w][tid];
            bincnt[tid] = acc;
        }
        __syncthreads();
        if (tid == 0) {
            int need = s_need, tot2 = 0;
            for (int b = 31; b >= 0; b--) {
                tot2 += (int)bincnt[b];
                if (tot2 >= need) { s_b2 = b; break; }
            }
        }
        __syncthreads();
        const int b2 = s_b2;
        for (int a = tid; a < AANCH; a += 512) {
            float s = cls[(size_t)a * NCLS + c];
            if (s > SCORE_TH) {
                int bin = bin_of(s);
                bool q = (bin > b1);
                if (bin == b1) {
                    int sub = min(max((int)((s - lo1) * (32.0f / w1)), 0), 31);
                    q = (sub >= b2);
                }
                if (q) {
                    int p = atomicAdd(&s_cnt, 1);
                    if (p < CAND)
                        keys[p] = ((u64)__float_as_uint(s) << 32) | (u32)(~(u32)a);
                }
            }
        }
    }
    __syncthreads();
    if (tid < NSUB) g_ccnt[c * NSUB + tid] = 0;   // reset for next replay

    // ---- bitonic sort descending (score desc, idx asc) ----
    for (int k = 2; k <= CAND; k <<= 1) {
        for (int j = k >> 1; j > 0; j >>= 1) {
#pragma unroll
            for (int p = 0; p < CAND / 512; p++) {
                int i = tid + p * 512;
                int ixj = i ^ j;
                if (ixj > i) {
                    u64 va = keys[i], vb = keys[ixj];
                    bool up = ((i & k) == 0);
                    if ((va < vb) == up) { keys[i] = vb; keys[ixj] = va; }
                }
            }
            __syncthreads();
        }
    }

    // ---- write candidate table (padded to 1024 with zero boxes) ----
#pragma unroll
    for (int p = 0; p < 2; p++) {
        int k = tid + p * 512;  // 0..1023
        u64 key = keys[k];
        bool valid = (k < TOPK) && (key != 0ull);
        float sc = -1.0f;
        float4 bx = make_float4(0.f, 0.f, 0.f, 0.f);
        float ar = 0.f;
        if (valid) {
            sc = __uint_as_float((u32)(key >> 32));
            u32 a = ~(u32)key;
            bx = ((const float4*)g_boxes)[a];
            ar = __fmul_rn(__fadd_rn(bx.z, -bx.x), __fadd_rn(bx.w, -bx.y));
        }
        int o = c * KPAD + k;
        g_cbox[o] = bx;
        g_car[o] = ar;
        g_csc[o] = sc;
        u32 bal = __ballot_sync(0xffffffffu, valid);
        if (lane == 0) g_valid[c * 32 + (k >> 5)] = bal;
    }
}

// ============================================================
// Kernel 3: suppression mask (proven IoU core), finer-grained grid.
// grid=(80,22), block=256. 176 warps x 3 tiles = 528 tiles/class.
// ============================================================
__global__ void __launch_bounds__(256)
mask_kernel() {
    __shared__ float4 bxy[KPAD];
    __shared__ float  sar[KPAD];
    const int c = blockIdx.x;
    const int tid = threadIdx.x, lane = tid & 31, warp = tid >> 5;

    for (int k = tid; k < KPAD; k += 256) {
        bxy[k] = g_cbox[c * KPAD + k];
        sar[k] = g_car[c * KPAD + k];
    }
    __syncthreads();

    const int warpGlobal = blockIdx.y * 8 + warp;   // 0..175
#pragma unroll 1
    for (int t = 0; t < 3; t++) {
        int tile = warpGlobal * 3 + t;              // 0..527
        int ib = (int)((65.0f - sqrtf(fmaxf(4225.0f - 8.0f * (float)tile, 0.0f))) * 0.5f);
        while (ib > 0 && ib * (65 - ib) / 2 > tile) ib--;
        while ((ib + 1) * (64 - ib) / 2 <= tile) ib++;
        int w = ib + (tile - ib * (65 - ib) / 2);

        int i = ib * 32 + lane;
        float4 ibx = bxy[i];
        float  ia  = sar[i];

        u32 myword = 0;
        const int jbase = w * 32;
#pragma unroll
        for (int jj = 0; jj < 32; jj++) {
            float4 jb = bxy[jbase + jj];   // broadcast
            float  ja = sar[jbase + jj];   // broadcast
            float xx1 = fmaxf(ibx.x, jb.x);
            float yy1 = fmaxf(ibx.y, jb.y);
            float xx2 = fminf(ibx.z, jb.z);
            float yy2 = fminf(ibx.w, jb.w);
            float iw = fmaxf(__fadd_rn(xx2, -xx1), 0.0f);
            float ih = fmaxf(__fadd_rn(yy2, -yy1), 0.0f);
            float inter = __fmul_rn(iw, ih);
            float tsum  = __fadd_rn(ia, ja);
            float t2    = __fadd_rn(tsum, -inter);
            float denom = __fadd_rn(t2, 1e-8f);
            float d2 = 0.5f * denom;                 // exact
            bool sup = inter > d2;
            if (sup) {
                if (__fadd_rn(inter, -d2) < 1e-6f * d2)
                    sup = (__fdiv_rn(inter, denom) > IOU_TH);  // exact near-tie
                if (sup) myword |= (1u << jj);
            }
        }
        if (ib == w) myword &= (0xFFFFFFFEu << lane);  // only j > i on diagonal
        g_mask[((size_t)c * 32 + w) * 1024 + ib * 32 + lane] = myword;
    }
}

// ============================================================
// Kernel 4: blocked greedy scan, direct-L2 with register ping-pong
// prefetch (no smem staging). Boolean-identical to R14's sparse resolve:
// diag words fetched via shfl of the prefetched register; skip-zero rows
// are no-ops; ffs order == serial order; diag clears only bits > row.
// ============================================================
#define LOAD_COL(BUF, WNEXT)                                              \
    {                                                                     \
        const uint4* _p = (const uint4*)(mbase + (size_t)lane * 1024 +    \
                                         (WNEXT) * 32);                   \
        _Pragma("unroll")                                                 \
        for (int _q = 0; _q < 8; _q++) {                                  \
            uint4 _v = _p[_q];                                            \
            BUF[_q * 4 + 0] = _v.x; BUF[_q * 4 + 1] = _v.y;               \
            BUF[_q * 4 + 2] = _v.z; BUF[_q * 4 + 3] = _v.w;               \
        }                                                                 \
    }

#define SCAN_STEP(W, COLBUF)                                              \
    {                                                                     \
        u32 nz = __ballot_sync(0xffffffffu, dcur != 0u);                  \
        u32 rv = __shfl_sync(0xffffffffu, remv, (W));                     \
        u32 keep = ~rv;                                                   \
        u32 pending = keep & nz;                                          \
        while (pending) {                                                 \
            int ii = __ffs(pending) - 1;                                  \
            u32 dii = __shfl_sync(0xffffffffu, dcur, ii);                 \
            keep &= ~dii;                                                 \
            pending = keep & nz & (0xFFFFFFFEu << ii);                    \
        }                                                                 \
        if (lane == (W)) keeplane = keep;                                 \
        if (lane > (W)) {                                                 \
            u32 a0 = 0, a1 = 0, a2 = 0, a3 = 0;                           \
            _Pragma("unroll")                                             \
            for (int ii = 0; ii < 32; ii += 4) {                          \
                u32 m0 = (u32)(-(int)((keep >> (ii + 0)) & 1u));          \
                u32 m1 = (u32)(-(int)((keep >> (ii + 1)) & 1u));          \
                u32 m2 = (u32)(-(int)((keep >> (ii + 2)) & 1u));          \
                u32 m3 = (u32)(-(int)((keep >> (ii + 3)) & 1u));          \
                a0 |= (m0 & COLBUF[ii + 0]);                              \
                a1 |= (m1 & COLBUF[ii + 1]);                              \
                a2 |= (m2 & COLBUF[ii + 2]);                              \
                a3 |= (m3 & COLBUF[ii + 3]);                              \
            }                                                             \
            remv |= (a0 | a1) | (a2 | a3);                                \
        }                                                                 \
    }

__global__ void __launch_bounds__(256)
scan_kernel(float* __restrict__ out, int out_size) {
    __shared__ u32 s_keep[32];
    const int c = blockIdx.x;
    const int tid = threadIdx.x;
    const u32* mbase = g_mask + (size_t)c * 32 * 1024;

    if (tid < 32) {
        const int lane = tid;
        u32 remv = ~g_valid[c * 32 + lane];
        u32 keeplane = 0;
        u32 colA[32], colB[32];
        u32 dcur, dnext;

        // preload step 0
        dcur = mbase[lane];            // word 0, rows 0..31
        LOAD_COL(colA, 0);

#pragma unroll 1
        for (int w = 0; w < 32; w += 2) {
            // prefetch step w+1
            dnext = mbase[(w + 1) * 1024 + (w + 1) * 32 + lane];
            LOAD_COL(colB, w + 1);
            SCAN_STEP(w, colA);
            dcur = dnext;
            // prefetch step w+2
            if (w + 2 < 32) {
                dnext = mbase[(w + 2) * 1024 + (w + 2) * 32 + lane];
                LOAD_COL(colA, w + 2);
            }
            SCAN_STEP(w + 1, colB);
            dcur = dnext;
        }
        s_keep[lane] = keeplane;
    }
    __syncthreads();

    for (int k = tid; k < TOPK; k += 256) {
        bool kp = (s_keep[k >> 5] >> (k & 31)) & 1u;
        int o = c * KPAD + k;
        float4 b = g_cbox[o];
        size_t ob = ((size_t)c * TOPK + k) * 5;
        if (ob + 5 <= (size_t)out_size) {
            out[ob + 0] = kp ? g_csc[o] : -1.0f;
            out[ob + 1] = kp ? b.x : 0.0f;
            out[ob + 2] = kp ? b.y : 0.0f;
            out[ob + 3] = kp ? b.z : 0.0f;
            out[ob + 4] = kp ? b.w : 0.0f;
        }
        int idg = 400000 + c * TOPK + k;
        if (idg < out_size) out[idg] = (float)c;
    }
}

// ============================================================
extern "C" void kernel_launch(void* const* d_in, const int* in_sizes, int n_in,
                              void* d_out, int out_size) {
    const float* cls     = (const float*)d_in[0];
    const float* regr    = (const float*)d_in[1];
    const float* anchors = (const float*)d_in[2];
    const int* ph = (n_in > 3) ? (const int*)d_in[3] : nullptr;
    const int* pw = (n_in > 4) ? (const int*)d_in[4] : nullptr;
    float* out = (float*)d_out;

    prep_kernel<<<DEC_BLOCKS + EMIT_BLOCKS, 256>>>(anchors, regr, cls, ph, pw);
    sortb_kernel<<<NCLS, 512>>>(cls);
    {
        dim3 grid(NCLS, 22);
        mask_kernel<<<grid, 256>>>();
    }
    scan_kernel<<<NCLS, 256>>>(out, out_size);
}

// round 16
// speedup vs baseline: 1.0712x; 1.0712x over previous
#include <cuda_runtime.h>
#include <cstdint>

#define AANCH 69354
#define APAD  69376
#define NCLS  80
#define TOPK  1000
#define KPAD  1024
#define CAND  2048
#define NSUB  8
#define SUBCAP 256
#define SCORE_TH 0.05f
#define IOU_TH   0.5f
#define T1GUESS  0.1955f

#define NELEM4     1387080         // AANCH*NCLS/4
#define DEC_BLOCKS 271             // ceil(AANCH/256)
#define EMIT_BLOCKS 5419           // ceil(NELEM4/256)

typedef unsigned int u32;
typedef unsigned long long u64;

// ---- device scratch (no allocations allowed) ----
__device__ float  g_boxes[AANCH * 4];
__device__ u64    g_cand[NCLS * NSUB * SUBCAP];   // 8 sub-buffers per class
__device__ int    g_ccnt[NCLS * NSUB];            // zero-init; reset by sortb
__device__ float4 g_cbox[NCLS * KPAD];
__device__ float  g_car[NCLS * KPAD];
__device__ float  g_csc[NCLS * KPAD];
__device__ u32    g_valid[NCLS * 32];
// mask transposed: [class][word 0..31][row 0..1023]
__device__ u32    g_mask[(size_t)NCLS * 32 * 1024];

// ============================================================
// Kernel 1: fused decode + candidate emission (8-way split counters)
// ============================================================
__global__ void __launch_bounds__(256)
prep_kernel(const float* __restrict__ anchors,
            const float* __restrict__ regr,
            const float* __restrict__ cls,
            const int* __restrict__ ph,
            const int* __restrict__ pw) {
    int b = blockIdx.x;
    if (b < DEC_BLOCKS) {
        int a = b * 256 + threadIdx.x;
        if (a >= AANCH) return;
        float W = pw ? (float)(*pw) : 608.0f;
        float H = ph ? (float)(*ph) : 608.0f;
        float4 an = ((const float4*)anchors)[a];
        float4 dl = ((const float4*)regr)[a];
        float w = an.z - an.x;
        float h = an.w - an.y;
        float cx = an.x + 0.5f * w;
        float cy = an.y + 0.5f * h;
        float dx = dl.x * 0.1f, dy = dl.y * 0.1f;
        float dw = dl.z * 0.2f, dh = dl.w * 0.2f;
        float pcx = cx + dx * w;
        float pcy = cy + dy * h;
        float pwid = expf(dw) * w;
        float phgt = expf(dh) * h;
        float x1 = fminf(fmaxf(pcx - 0.5f * pwid, 0.0f), W);
        float y1 = fminf(fmaxf(pcy - 0.5f * phgt, 0.0f), H);
        float x2 = fminf(fmaxf(pcx + 0.5f * pwid, 0.0f), W);
        float y2 = fminf(fmaxf(pcy + 0.5f * phgt, 0.0f), H);
        ((float4*)g_boxes)[a] = make_float4(x1, y1, x2, y2);
    } else {
        int i = (b - DEC_BLOCKS) * 256 + threadIdx.x;   // float4 index
        const int sub = b & 7;
        if (i < NELEM4) {
            float4 v = ((const float4*)cls)[i];
            int e = i * 4;
            int a = e / NCLS;
            int c = e % NCLS;          // NCLS%4==0 -> c in {0,4,...,76}
#pragma unroll
            for (int q = 0; q < 4; q++) {
                float s = (q == 0) ? v.x : (q == 1) ? v.y : (q == 2) ? v.z : v.w;
                if (s > T1GUESS) {
                    int slot = (c + q) * NSUB + sub;
                    int p = atomicAdd(&g_ccnt[slot], 1);
                    if (p < SUBCAP)
                        g_cand[slot * SUBCAP + p] =
                            ((u64)__float_as_uint(s) << 32) | (u32)(~(u32)a);
                }
            }
        }
    }
}

// ============================================================
// Kernel 2: per-class segment-load + sort + candidate tables.
// grid=80, block=512.
// ============================================================
__device__ __forceinline__ int bin_of(float s) {
    int b = (int)((s - SCORE_TH) * (32.0f / 0.15f));
    return min(max(b, 0), 31);
}

__global__ void __launch_bounds__(512)
sortb_kernel(const float* __restrict__ cls) {
    __shared__ u64 keys[CAND];
    __shared__ u32 bincnt[32];
    __shared__ u32 wbin[16][32];
    __shared__ int s_cnts[NSUB], s_off[NSUB], s_ok;
    __shared__ int s_cnt, s_b1, s_need, s_b2;

    const int c = blockIdx.x;
    const int tid = threadIdx.x, lane = tid & 31, warp = tid >> 5;

    if (tid < NSUB) s_cnts[tid] = g_ccnt[c * NSUB + tid];
    __syncthreads();
    if (tid == 0) {
        int tot = 0, ovf = 0;
        for (int s = 0; s < NSUB; s++) {
            s_off[s] = tot;
            if (s_cnts[s] > SUBCAP) ovf = 1;
            tot += min(s_cnts[s], SUBCAP);
        }
        s_cnt = tot;
        s_ok = (!ovf && tot >= TOPK && tot <= CAND) ? 1 : 0;
    }
    __syncthreads();
    const bool ok = (s_ok != 0);

    for (int i = tid; i < CAND; i += 512) keys[i] = 0ull;
    __syncthreads();

    if (ok) {
        // concatenate the 8 segments
#pragma unroll
        for (int s = 0; s < NSUB; s++) {
            int n = min(s_cnts[s], SUBCAP);
            int off = s_off[s];
            const u64* seg = g_cand + (c * NSUB + s) * SUBCAP;
            for (int i = tid; i < n; i += 512) keys[off + i] = seg[i];
        }
    } else {
        // ---- exact fallback: 2-level ballot histogram on strided cls ----
        if (tid == 0) s_cnt = 0;
        __syncthreads();
        const int NITER = (APAD + 511) / 512;
        {
            u32 bc = 0;
            for (int it = 0; it < NITER; it++) {
                int a = tid + it * 512;
                float s = (a < AANCH) ? cls[(size_t)a * NCLS + c] : -1.0f;
                bool ir = s > SCORE_TH;
                int bin = ir ? bin_of(s) : 0;
                u32 m = __ballot_sync(0xffffffffu, ir);
#pragma unroll
                for (int bb = 0; bb < 5; bb++) {
                    u32 vb = __ballot_sync(0xffffffffu, (bin >> bb) & 1);
                    m &= ((lane >> bb) & 1) ? vb : ~vb;
                }
                bc += __popc(m);
            }
            wbin[warp][lane] = bc;
        }
        __syncthreads();
        if (tid < 32) {
            u32 acc = 0;
#pragma unroll
            for (int w = 0; w < 16; w++) acc += wbin[w][tid];
            bincnt[tid] = acc;
        }
        __syncthreads();
        if (tid == 0) {
            int tot = 0, b1 = 0, found = 0;
            for (int b = 31; b >= 0; b--) {
                if (tot + (int)bincnt[b] >= TOPK) { b1 = b; found = 1; break; }
                tot += (int)bincnt[b];
            }
            s_b1 = found ? b1 : 0;
            s_need = TOPK - tot;
            s_b2 = 0;
        }
        __syncthreads();
        const int b1 = s_b1;
        const float w1 = 0.15f / 32.0f;
        const float lo1 = SCORE_TH + b1 * w1;
        {
            u32 bc = 0;
            for (int it = 0; it < NITER; it++) {
                int a = tid + it * 512;
                float s = (a < AANCH) ? cls[(size_t)a * NCLS + c] : -1.0f;
                bool ir = s > SCORE_TH;
                bool inb = ir && (bin_of(s) == b1);
                int sub = 0;
                if (inb) sub = min(max((int)((s - lo1) * (32.0f / w1)), 0), 31);
                u32 m = __ballot_sync(0xffffffffu, inb);
#pragma unroll
                for (int bb = 0; bb < 5; bb++) {
                    u32 vb = __ballot_sync(0xffffffffu, (sub >> bb) & 1);
                    m &= ((lane >> bb) & 1) ? vb : ~vb;
                }
                bc += __popc(m);
            }
            wbin[warp][lane] = bc;
        }
        __syncthreads();
        if (tid < 32) {
            u32 acc = 0;
#pragma unroll
            for (int w = 0; w < 16; w++) acc += wbin[w][tid];
            bincnt[tid] = acc;
        }
        __syncthreads();
        if (tid == 0) {
            int need = s_need, tot2 = 0;
            for (int b = 31; b >= 0; b--) {
                tot2 += (int)bincnt[b];
                if (tot2 >= need) { s_b2 = b; break; }
            }
        }
        __syncthreads();
        const int b2 = s_b2;
        for (int a = tid; a < AANCH; a += 512) {
            float s = cls[(size_t)a * NCLS + c];
            if (s > SCORE_TH) {
                int bin = bin_of(s);
                bool q = (bin > b1);
                if (bin == b1) {
                    int sub = min(max((int)((s - lo1) * (32.0f / w1)), 0), 31);
                    q = (sub >= b2);
                }
                if (q) {
                    int p = atomicAdd(&s_cnt, 1);
                    if (p < CAND)
                        keys[p] = ((u64)__float_as_uint(s) << 32) | (u32)(~(u32)a);
                }
            }
        }
    }
    __syncthreads();
    if (tid < NSUB) g_ccnt[c * NSUB + tid] = 0;   // reset for next replay

    // ---- bitonic sort descending (score desc, idx asc) ----
    for (int k = 2; k <= CAND; k <<= 1) {
        for (int j = k >> 1; j > 0; j >>= 1) {
#pragma unroll
            for (int p = 0; p < CAND / 512; p++) {
                int i = tid + p * 512;
                int ixj = i ^ j;
                if (ixj > i) {
                    u64 va = keys[i], vb = keys[ixj];
                    bool up = ((i & k) == 0);
                    if ((va < vb) == up) { keys[i] = vb; keys[ixj] = va; }
                }
            }
            __syncthreads();
        }
    }

    // ---- write candidate table (padded to 1024 with zero boxes) ----
#pragma unroll
    for (int p = 0; p < 2; p++) {
        int k = tid + p * 512;  // 0..1023
        u64 key = keys[k];
        bool valid = (k < TOPK) && (key != 0ull);
        float sc = -1.0f;
        float4 bx = make_float4(0.f, 0.f, 0.f, 0.f);
        float ar = 0.f;
        if (valid) {
            sc = __uint_as_float((u32)(key >> 32));
            u32 a = ~(u32)key;
            bx = ((const float4*)g_boxes)[a];
            ar = __fmul_rn(__fadd_rn(bx.z, -bx.x), __fadd_rn(bx.w, -bx.y));
        }
        int o = c * KPAD + k;
        g_cbox[o] = bx;
        g_car[o] = ar;
        g_csc[o] = sc;
        u32 bal = __ballot_sync(0xffffffffu, valid);
        if (lane == 0) g_valid[c * 32 + (k >> 5)] = bal;
    }
}

// ============================================================
// Kernel 3: suppression mask (proven IoU core), finer-grained grid.
// grid=(80,22), block=256. 176 warps x 3 tiles = 528 tiles/class.
// ============================================================
__global__ void __launch_bounds__(256)
mask_kernel() {
    __shared__ float4 bxy[KPAD];
    __shared__ float  sar[KPAD];
    const int c = blockIdx.x;
    const int tid = threadIdx.x, lane = tid & 31, warp = tid >> 5;

    for (int k = tid; k < KPAD; k += 256) {
        bxy[k] = g_cbox[c * KPAD + k];
        sar[k] = g_car[c * KPAD + k];
    }
    __syncthreads();

    const int warpGlobal = blockIdx.y * 8 + warp;   // 0..175
#pragma unroll 1
    for (int t = 0; t < 3; t++) {
        int tile = warpGlobal * 3 + t;              // 0..527
        int ib = (int)((65.0f - sqrtf(fmaxf(4225.0f - 8.0f * (float)tile, 0.0f))) * 0.5f);
        while (ib > 0 && ib * (65 - ib) / 2 > tile) ib--;
        while ((ib + 1) * (64 - ib) / 2 <= tile) ib++;
        int w = ib + (tile - ib * (65 - ib) / 2);

        int i = ib * 32 + lane;
        float4 ibx = bxy[i];
        float  ia  = sar[i];

        u32 myword = 0;
        const int jbase = w * 32;
#pragma unroll
        for (int jj = 0; jj < 32; jj++) {
            float4 jb = bxy[jbase + jj];   // broadcast
            float  ja = sar[jbase + jj];   // broadcast
            float xx1 = fmaxf(ibx.x, jb.x);
            float yy1 = fmaxf(ibx.y, jb.y);
            float xx2 = fminf(ibx.z, jb.z);
            float yy2 = fminf(ibx.w, jb.w);
            float iw = fmaxf(__fadd_rn(xx2, -xx1), 0.0f);
            float ih = fmaxf(__fadd_rn(yy2, -yy1), 0.0f);
            float inter = __fmul_rn(iw, ih);
            float tsum  = __fadd_rn(ia, ja);
            float t2    = __fadd_rn(tsum, -inter);
            float denom = __fadd_rn(t2, 1e-8f);
            float d2 = 0.5f * denom;                 // exact
            bool sup = inter > d2;
            if (sup) {
                if (__fadd_rn(inter, -d2) < 1e-6f * d2)
                    sup = (__fdiv_rn(inter, denom) > IOU_TH);  // exact near-tie
                if (sup) myword |= (1u << jj);
            }
        }
        if (ib == w) myword &= (0xFFFFFFFEu << lane);  // only j > i on diagonal
        g_mask[((size_t)c * 32 + w) * 1024 + ib * 32 + lane] = myword;
    }
}

// ============================================================
// Kernel 4: blocked greedy scan on SMEM-staged mask (R14, proven) with
// upper-triangle-only staging: word w is only ever read for rows
// < 32*(w+1) (diag tile + column blocks), so stage just that half
// (66KB of traffic instead of 131KB). Resolve identical to R14.
// ============================================================
#define MSTRIDE 1025
#define SCAN_SMEM (32 * MSTRIDE * 4)

__global__ void __launch_bounds__(256)
scan_kernel(float* __restrict__ out, int out_size) {
    extern __shared__ u32 maskS[];   // [32][MSTRIDE]
    __shared__ u32 s_keep[32];
    const int c = blockIdx.x;
    const int tid = threadIdx.x, lane = tid & 31, warp = tid >> 5;
    const u32* mbase = g_mask + (size_t)c * 32 * 1024;

    // stage upper-triangle only: warp handles words w = warp, warp+8, ...
    // word w needs rows [0, 32*(w+1)) = (w+1)*8 uint4 chunks.
    for (int w = warp; w < 32; w += 8) {
        const uint4* src = (const uint4*)(mbase + w * 1024);
        int n4 = (w + 1) * 8;
        for (int i4 = lane; i4 < n4; i4 += 32) {
            uint4 v = src[i4];
            u32* dst = maskS + w * MSTRIDE + i4 * 4;
            dst[0] = v.x; dst[1] = v.y; dst[2] = v.z; dst[3] = v.w;
        }
    }
    __syncthreads();

    if (tid < 32) {
        u32 remv = ~g_valid[c * 32 + lane];
        u32 keeplane = 0;

#pragma unroll 1
        for (int w = 0; w < 32; w++) {
            const u32* diag = maskS + w * MSTRIDE + w * 32;
            u32 dval = diag[lane];
            u32 nz = __ballot_sync(0xffffffffu, dval != 0u);
            u32 rv = __shfl_sync(0xffffffffu, remv, w);
            // sparse serial resolve — uniform across lanes (broadcast LDS)
            u32 keep = ~rv;
            u32 pending = keep & nz;
            while (pending) {
                int ii = __ffs(pending) - 1;
                keep &= ~diag[ii];
                pending = keep & nz & (0xFFFFFFFEu << ii);
            }
            u32 kept = keep;
            if (lane == w) keeplane = kept;
            // branchless column update, 4 independent accumulators
            if (lane > w) {
                const u32* col = maskS + lane * MSTRIDE + w * 32;
                u32 a0 = 0, a1 = 0, a2 = 0, a3 = 0;
#pragma unroll
                for (int ii = 0; ii < 32; ii += 4) {
                    u32 m0 = (u32)(-(int)((kept >> (ii + 0)) & 1u));
                    u32 m1 = (u32)(-(int)((kept >> (ii + 1)) & 1u));
                    u32 m2 = (u32)(-(int)((kept >> (ii + 2)) & 1u));
                    u32 m3 = (u32)(-(int)((kept >> (ii + 3)) & 1u));
                    a0 |= (m0 & col[ii + 0]);
                    a1 |= (m1 & col[ii + 1]);
                    a2 |= (m2 & col[ii + 2]);
                    a3 |= (m3 & col[ii + 3]);
                }
                remv |= (a0 | a1) | (a2 | a3);
            }
        }
        s_keep[lane] = keeplane;
    }
    __syncthreads();

    for (int k = tid; k < TOPK; k += 256) {
        bool kp = (s_keep[k >> 5] >> (k & 31)) & 1u;
        int o = c * KPAD + k;
        float4 b = g_cbox[o];
        size_t ob = ((size_t)c * TOPK + k) * 5;
        if (ob + 5 <= (size_t)out_size) {
            out[ob + 0] = kp ? g_csc[o] : -1.0f;
            out[ob + 1] = kp ? b.x : 0.0f;
            out[ob + 2] = kp ? b.y : 0.0f;
            out[ob + 3] = kp ? b.z : 0.0f;
            out[ob + 4] = kp ? b.w : 0.0f;
        }
        int idg = 400000 + c * TOPK + k;
        if (idg < out_size) out[idg] = (float)c;
    }
}

// ============================================================
extern "C" void kernel_launch(void* const* d_in, const int* in_sizes, int n_in,
                              void* d_out, int out_size) {
    const float* cls     = (const float*)d_in[0];
    const float* regr    = (const float*)d_in[1];
    const float* anchors = (const float*)d_in[2];
    const int* ph = (n_in > 3) ? (const int*)d_in[3] : nullptr;
    const int* pw = (n_in > 4) ? (const int*)d_in[4] : nullptr;
    float* out = (float*)d_out;

    cudaFuncSetAttribute(scan_kernel,
                         cudaFuncAttributeMaxDynamicSharedMemorySize,
                         SCAN_SMEM);

    prep_kernel<<<DEC_BLOCKS + EMIT_BLOCKS, 256>>>(anchors, regr, cls, ph, pw);
    sortb_kernel<<<NCLS, 512>>>(cls);
    {
        dim3 grid(NCLS, 22);
        mask_kernel<<<grid, 256>>>();
    }
    scan_kernel<<<NCLS, 256, SCAN_SMEM>>>(out, out_size);
}